// round 1
// baseline (speedup 1.0000x reference)
#include <cuda_runtime.h>
#include <math.h>

// Problem constants (MoELayer_47193100648722): N=8192 tokens, D=2048, H=2048, E=8, top-2.
#define NTOK 8192
#define DDIM 2048
#define HDIM 2048
#define NEXP 8

// Scratch (device globals: no cudaMalloc allowed).
__device__ int   g_cnt[NEXP];
__device__ int   g_tok[NEXP * NTOK];
__device__ float g_wt [NEXP * NTOK];

// ---------------------------------------------------------------------------
// Kernel 0a: zero expert counters
// ---------------------------------------------------------------------------
__global__ void k_zero_cnt() {
    if (threadIdx.x < NEXP) g_cnt[threadIdx.x] = 0;
}

// ---------------------------------------------------------------------------
// Kernel 0b: zero output (harness poisons d_out with 0xAA)
// ---------------------------------------------------------------------------
__global__ void k_zero_out(float4* __restrict__ out, int n4) {
    int i = blockIdx.x * blockDim.x + threadIdx.x;
    if (i < n4) out[i] = make_float4(0.f, 0.f, 0.f, 0.f);
}

// ---------------------------------------------------------------------------
// Kernel 1: gating. One warp per token.
//   logits = x @ Wg + bg ; softmax ; top-2 (ties -> lowest index, matching
//   jax.lax.top_k) ; append (token, weight) to each chosen expert's list.
// ---------------------------------------------------------------------------
__global__ void k_gate(const float* __restrict__ x,
                       const float* __restrict__ Wg,
                       const float* __restrict__ bg) {
    int gwarp = (blockIdx.x * blockDim.x + threadIdx.x) >> 5;
    int lane  = threadIdx.x & 31;
    if (gwarp >= NTOK) return;

    const float* xr = x + (size_t)gwarp * DDIM;
    float acc[NEXP];
#pragma unroll
    for (int e = 0; e < NEXP; e++) acc[e] = 0.f;

    for (int d = lane; d < DDIM; d += 32) {
        float xv = xr[d];
        const float4* wr = (const float4*)(Wg + (size_t)d * NEXP);
        float4 w0 = wr[0];
        float4 w1 = wr[1];
        acc[0] += xv * w0.x;  acc[1] += xv * w0.y;
        acc[2] += xv * w0.z;  acc[3] += xv * w0.w;
        acc[4] += xv * w1.x;  acc[5] += xv * w1.y;
        acc[6] += xv * w1.z;  acc[7] += xv * w1.w;
    }

#pragma unroll
    for (int e = 0; e < NEXP; e++) {
#pragma unroll
        for (int o = 16; o > 0; o >>= 1)
            acc[e] += __shfl_xor_sync(0xFFFFFFFFu, acc[e], o);
    }

    if (lane == 0) {
#pragma unroll
        for (int e = 0; e < NEXP; e++) acc[e] += bg[e];

        // top-1
        float m1 = acc[0]; int i1 = 0;
#pragma unroll
        for (int e = 1; e < NEXP; e++)
            if (acc[e] > m1) { m1 = acc[e]; i1 = e; }
        // top-2 (exclude i1)
        float m2 = -INFINITY; int i2 = 0;
#pragma unroll
        for (int e = 0; e < NEXP; e++) {
            if (e == i1) continue;
            if (acc[e] > m2) { m2 = acc[e]; i2 = e; }
        }

        // softmax values at the two selected experts
        float s = 0.f;
#pragma unroll
        for (int e = 0; e < NEXP; e++) s += __expf(acc[e] - m1);
        float inv = 1.f / s;
        float w1v = inv;                    // exp(m1-m1)/s
        float w2v = __expf(m2 - m1) * inv;

        int p1 = atomicAdd(&g_cnt[i1], 1);
        g_tok[i1 * NTOK + p1] = gwarp;
        g_wt [i1 * NTOK + p1] = w1v;
        int p2 = atomicAdd(&g_cnt[i2], 1);
        g_tok[i2 * NTOK + p2] = gwarp;
        g_wt [i2 * NTOK + p2] = w2v;
    }
}

// ---------------------------------------------------------------------------
// Kernel 2: grouped expert GEMM.
//   For expert e with cnt[e] assigned tokens:
//     out[tok, :] += w * (x[tok, :] @ We[e] + be[e])
//   Tiles: BM=128 tokens x BN=128 H, BK=16, 256 threads, 8x8 microtile.
//   Output accumulated with atomicAdd (each token touched by exactly 2 experts).
// ---------------------------------------------------------------------------
#define BM 128
#define BN 128
#define BK 16
#define LDA 132   // padded leading dim for As (16B-aligned, reduces STS conflicts)

__global__ __launch_bounds__(256, 2)
void k_moe_gemm(const float* __restrict__ x,
                const float* __restrict__ We,
                const float* __restrict__ be,
                float* __restrict__ out) {
    const int e   = blockIdx.z;
    const int cnt = g_cnt[e];
    const int m0  = blockIdx.y * BM;
    if (m0 >= cnt) return;
    const int n0  = blockIdx.x * BN;

    __shared__ float As[BK][LDA];   // A transposed: As[k][m]
    __shared__ float Bs[BK][BN];    // Bs[k][n]
    __shared__ int   s_tok[BM];
    __shared__ float s_w[BM];

    const int tid = threadIdx.x;
    const int tx  = tid & 15;
    const int ty  = tid >> 4;

    if (tid < BM) {
        int r = m0 + tid;
        if (r < cnt) {
            s_tok[tid] = g_tok[e * NTOK + r];
            s_w[tid]   = g_wt [e * NTOK + r];
        } else {
            s_tok[tid] = -1;
            s_w[tid]   = 0.f;
        }
    }
    __syncthreads();

    float acc[8][8];
#pragma unroll
    for (int i = 0; i < 8; i++)
#pragma unroll
        for (int j = 0; j < 8; j++) acc[i][j] = 0.f;

    const float* Wb = We + (size_t)e * DDIM * HDIM;

    for (int k0 = 0; k0 < DDIM; k0 += BK) {
        // Load A (gathered token rows), store transposed As[k][m].
#pragma unroll
        for (int i = 0; i < 8; i++) {
            int lin = tid + i * 256;
            int m   = lin >> 4;
            int kk  = lin & 15;
            int t   = s_tok[m];
            As[kk][m] = (t >= 0) ? x[(size_t)t * DDIM + k0 + kk] : 0.f;
        }
        // Load B tile (coalesced along H).
#pragma unroll
        for (int i = 0; i < 8; i++) {
            int lin = tid + i * 256;
            int kk  = lin >> 7;
            int n   = lin & 127;
            Bs[kk][n] = Wb[(size_t)(k0 + kk) * HDIM + n0 + n];
        }
        __syncthreads();

#pragma unroll
        for (int kk = 0; kk < BK; kk++) {
            float a[8], b[8];
            *(float4*)(a)     = *(const float4*)&As[kk][ty * 4];
            *(float4*)(a + 4) = *(const float4*)&As[kk][ty * 4 + 64];
            *(float4*)(b)     = *(const float4*)&Bs[kk][tx * 4];
            *(float4*)(b + 4) = *(const float4*)&Bs[kk][tx * 4 + 64];
#pragma unroll
            for (int i = 0; i < 8; i++)
#pragma unroll
                for (int j = 0; j < 8; j++)
                    acc[i][j] += a[i] * b[j];
        }
        __syncthreads();
    }

    // Epilogue: out[tok, h] += w * (acc + be[e, h])
    const float* bb = be + (size_t)e * HDIM;
#pragma unroll
    for (int i = 0; i < 8; i++) {
        int m = ty * 4 + (i & 3) + ((i >> 2) * 64);
        int t = s_tok[m];
        if (t < 0) continue;
        float w = s_w[m];
        float* orow = out + (size_t)t * HDIM;
#pragma unroll
        for (int j = 0; j < 8; j++) {
            int h = n0 + tx * 4 + (j & 3) + ((j >> 2) * 64);
            atomicAdd(&orow[h], w * (acc[i][j] + bb[h]));
        }
    }
}

// ---------------------------------------------------------------------------
// Launch
// ---------------------------------------------------------------------------
extern "C" void kernel_launch(void* const* d_in, const int* in_sizes, int n_in,
                              void* d_out, int out_size) {
    const float* x  = (const float*)d_in[0];   // [N, D]
    const float* Wg = (const float*)d_in[1];   // [D, E]
    const float* bg = (const float*)d_in[2];   // [E]
    const float* We = (const float*)d_in[3];   // [E, D, H]
    const float* be = (const float*)d_in[4];   // [E, H]
    float* out = (float*)d_out;                // [N, H]

    (void)in_sizes; (void)n_in;

    // 0) reset counters + zero output
    k_zero_cnt<<<1, 32>>>();
    int n4 = out_size / 4;
    k_zero_out<<<(n4 + 255) / 256, 256>>>((float4*)out, n4);

    // 1) gating (one warp per token; 8 warps per block)
    k_gate<<<NTOK / 8, 256>>>(x, Wg, bg);

    // 2) grouped expert GEMM
    dim3 grid(HDIM / BN, (NTOK + BM - 1) / BM, NEXP);
    k_moe_gemm<<<grid, 256>>>(x, We, be, out);
}

// round 4
// speedup vs baseline: 5.5461x; 5.5461x over previous
#include <cuda_runtime.h>
#include <math.h>
#include <stdint.h>

// MoELayer_47193100648722: N=8192 tokens, D=2048, H=2048, E=8, top-2, fp32.
#define NTOK 8192
#define DDIM 2048
#define HDIM 2048
#define NEXP 8

#define BM 128
#define BN 128
#define BK 32
#define STAGES 3
#define NITER (DDIM / BK)   // 64

// ---------------------------------------------------------------------------
// Device scratch (no cudaMalloc allowed)
// ---------------------------------------------------------------------------
__device__ int   g_cnt[NEXP];
__device__ int   g_tok[NEXP * NTOK];
__device__ float g_wt [NEXP * NTOK];
__device__ float g_We_t[(size_t)NEXP * DDIM * HDIM];  // [e][h][d], tf32-rounded
__device__ float g_x_r [(size_t)NTOK * DDIM];         // x, tf32-rounded

// ---------------------------------------------------------------------------
// Helpers (base sm_103-safe: mma.sync / ldmatrix / cp.async only)
// ---------------------------------------------------------------------------
__device__ __forceinline__ uint32_t smem_u32(const void* p) {
    return (uint32_t)__cvta_generic_to_shared(p);
}
__device__ __forceinline__ float cvt_tf32(float x) {
    float r; asm("cvt.rna.tf32.f32 %0, %1;" : "=f"(r) : "f"(x)); return r;
}
__device__ __forceinline__ void cp16(uint32_t dst, const void* src) {
    asm volatile("cp.async.cg.shared.global [%0], [%1], 16;" :: "r"(dst), "l"(src));
}
#define CP_COMMIT() asm volatile("cp.async.commit_group;" ::: "memory")
#define SWZ(o) ((o) ^ (((o) >> 3) & 0x70))

#define LDSM4(R0, R1, R2, R3, addr)                                          \
    asm volatile("ldmatrix.sync.aligned.m8n8.x4.shared.b16 {%0,%1,%2,%3}, [%4];" \
                 : "=r"(R0), "=r"(R1), "=r"(R2), "=r"(R3) : "r"(addr))

#define MMA_TF32(d, a, b)                                                    \
    asm volatile("mma.sync.aligned.m16n8k8.row.col.f32.tf32.tf32.f32 "       \
                 "{%0,%1,%2,%3}, {%4,%5,%6,%7}, {%8,%9}, {%0,%1,%2,%3};"     \
                 : "+f"((d)[0]), "+f"((d)[1]), "+f"((d)[2]), "+f"((d)[3])    \
                 : "r"((a)[0]), "r"((a)[1]), "r"((a)[2]), "r"((a)[3]),       \
                   "r"((b)[0]), "r"((b)[1]))

// ---------------------------------------------------------------------------
// Kernel 0a/0b: zero counters / output
// ---------------------------------------------------------------------------
__global__ void k_zero_cnt() {
    if (threadIdx.x < NEXP) g_cnt[threadIdx.x] = 0;
}
__global__ void k_zero_out(float4* __restrict__ out, int n4) {
    int i = blockIdx.x * blockDim.x + threadIdx.x;
    if (i < n4) out[i] = make_float4(0.f, 0.f, 0.f, 0.f);
}

// ---------------------------------------------------------------------------
// Kernel R: round x to tf32 (rna) into g_x_r
// ---------------------------------------------------------------------------
__global__ void k_round_x(const float4* __restrict__ x, int n4) {
    int i = blockIdx.x * blockDim.x + threadIdx.x;
    if (i < n4) {
        float4 v = x[i];
        v.x = cvt_tf32(v.x); v.y = cvt_tf32(v.y);
        v.z = cvt_tf32(v.z); v.w = cvt_tf32(v.w);
        ((float4*)g_x_r)[i] = v;
    }
}

// ---------------------------------------------------------------------------
// Kernel T: transpose We[e][d][h] -> g_We_t[e][h][d], tf32-rounded
// ---------------------------------------------------------------------------
__global__ void k_transpose(const float* __restrict__ We) {
    __shared__ float tile[32][33];
    int e = blockIdx.z;
    int d0 = blockIdx.x * 32, h0 = blockIdx.y * 32;
    const float* src = We + (size_t)e * DDIM * HDIM;
    float* dst = g_We_t + (size_t)e * HDIM * DDIM;
    int tx = threadIdx.x, ty = threadIdx.y;
#pragma unroll
    for (int j = 0; j < 4; j++)
        tile[ty + j * 8][tx] = src[(size_t)(d0 + ty + j * 8) * HDIM + h0 + tx];
    __syncthreads();
#pragma unroll
    for (int j = 0; j < 4; j++)
        dst[(size_t)(h0 + ty + j * 8) * DDIM + d0 + tx] = cvt_tf32(tile[tx][ty + j * 8]);
}

// ---------------------------------------------------------------------------
// Kernel 1: gating (one warp per token) — softmax, top-2, per-expert lists
// ---------------------------------------------------------------------------
__global__ void k_gate(const float* __restrict__ x,
                       const float* __restrict__ Wg,
                       const float* __restrict__ bg) {
    int gwarp = (blockIdx.x * blockDim.x + threadIdx.x) >> 5;
    int lane  = threadIdx.x & 31;
    if (gwarp >= NTOK) return;

    const float* xr = x + (size_t)gwarp * DDIM;
    float acc[NEXP];
#pragma unroll
    for (int e = 0; e < NEXP; e++) acc[e] = 0.f;

    for (int d = lane; d < DDIM; d += 32) {
        float xv = xr[d];
        const float4* wr = (const float4*)(Wg + (size_t)d * NEXP);
        float4 w0 = wr[0];
        float4 w1 = wr[1];
        acc[0] += xv * w0.x;  acc[1] += xv * w0.y;
        acc[2] += xv * w0.z;  acc[3] += xv * w0.w;
        acc[4] += xv * w1.x;  acc[5] += xv * w1.y;
        acc[6] += xv * w1.z;  acc[7] += xv * w1.w;
    }
#pragma unroll
    for (int e = 0; e < NEXP; e++) {
#pragma unroll
        for (int o = 16; o > 0; o >>= 1)
            acc[e] += __shfl_xor_sync(0xFFFFFFFFu, acc[e], o);
    }
    if (lane == 0) {
#pragma unroll
        for (int e = 0; e < NEXP; e++) acc[e] += bg[e];
        float m1 = acc[0]; int i1 = 0;
#pragma unroll
        for (int e = 1; e < NEXP; e++)
            if (acc[e] > m1) { m1 = acc[e]; i1 = e; }
        float m2 = -INFINITY; int i2 = 0;
#pragma unroll
        for (int e = 0; e < NEXP; e++) {
            if (e == i1) continue;
            if (acc[e] > m2) { m2 = acc[e]; i2 = e; }
        }
        float s = 0.f;
#pragma unroll
        for (int e = 0; e < NEXP; e++) s += __expf(acc[e] - m1);
        float inv = 1.f / s;
        float w1v = inv;
        float w2v = __expf(m2 - m1) * inv;

        int p1 = atomicAdd(&g_cnt[i1], 1);
        g_tok[i1 * NTOK + p1] = gwarp;
        g_wt [i1 * NTOK + p1] = w1v;
        int p2 = atomicAdd(&g_cnt[i2], 1);
        g_tok[i2 * NTOK + p2] = gwarp;
        g_wt [i2 * NTOK + p2] = w2v;
    }
}

// ---------------------------------------------------------------------------
// Kernel 2: grouped expert GEMM — mma.sync tf32, 3-stage cp.async pipeline.
//   C[128 tok x 128 h] per CTA. 8 warps in 2(m) x 4(n), each 64x32.
// SMEM: 3 stages x (A 16KB + B 16KB) = 96KB, then s_tok/s_w/s_be.
// ---------------------------------------------------------------------------
#define SM_STAGE 32768
#define SM_TOK   (STAGES * SM_STAGE)          // 98304
#define SM_W     (SM_TOK + 512)
#define SM_BE    (SM_W + 512)
#define SMEM_BYTES (SM_BE + 512)

__global__ void __launch_bounds__(256, 2)
k_moe_gemm(const float* __restrict__ be, float* __restrict__ out) {
    extern __shared__ char dsm[];
    const int e   = blockIdx.z;
    const int cnt = g_cnt[e];
    const int m0  = blockIdx.y * BM;
    if (m0 >= cnt) return;
    const int n0  = blockIdx.x * BN;
    const int tid = threadIdx.x;
    const uint32_t sb = smem_u32(dsm);

    int*   s_tok = (int*)(dsm + SM_TOK);
    float* s_w   = (float*)(dsm + SM_W);
    float* s_be  = (float*)(dsm + SM_BE);

    if (tid < BM) {
        int r = m0 + tid;
        int t; float w;
        if (r < cnt) { t = g_tok[e * NTOK + r]; w = g_wt[e * NTOK + r]; }
        else         { t = -1; w = 0.f; }
        s_tok[tid] = t; s_w[tid] = w;
        s_be[tid]  = be[e * HDIM + n0 + tid];
    }
    __syncthreads();

    // Per-thread cp.async source pointers + swizzled dst offsets (fixed per k-iter).
    const char* gA[4]; const char* gB[4];
    uint32_t dA[4], dB[4];
    {
        const int c8 = (tid & 7) * 16;   // byte offset within a 128B row
#pragma unroll
        for (int j = 0; j < 4; j++) {
            int row = (tid + j * 256) >> 3;   // 0..127
            int t = s_tok[row]; if (t < 0) t = 0;  // garbage row, masked in epilogue
            gA[j] = (const char*)(g_x_r + (size_t)t * DDIM) + c8;
            dA[j] = sb + SWZ(row * 128 + c8);
            gB[j] = (const char*)(g_We_t + ((size_t)e * HDIM + n0 + row) * DDIM) + c8;
            dB[j] = sb + 16384 + SWZ(row * 128 + c8);
        }
    }

    // ldmatrix raw offsets + per-thread constant swizzle XOR masks.
    // Correct address = (raw + i*2048 + kk*32) ^ X, where X = (raw>>3)&0x70 is
    // invariant under both offsets (row%8 unchanged; adds never carry past bit 6).
    const int lane = tid & 31, warp = tid >> 5;
    const int wm = (warp & 1) * 64, wn = (warp >> 1) * 32;
    const int lr = lane & 7, q = lane >> 3;
    const uint32_t aRaw = (uint32_t)(wm + lr + 8 * (q & 1)) * 128 + 16 * (q >> 1);
    const uint32_t aX   = (aRaw >> 3) & 0x70;
    const uint32_t bRaw = (uint32_t)(wn + lr + 8 * (q >> 1)) * 128 + 16 * (q & 1);
    const uint32_t bX   = (bRaw >> 3) & 0x70;

    float acc[4][4][4];
#pragma unroll
    for (int i = 0; i < 4; i++)
#pragma unroll
        for (int j = 0; j < 4; j++)
#pragma unroll
            for (int c = 0; c < 4; c++) acc[i][j][c] = 0.f;

    // Prologue: stages 0..STAGES-2
#pragma unroll
    for (int s = 0; s < STAGES - 1; s++) {
        const int off = s * 128;                 // BK*4 bytes per k-iter
        const uint32_t so = s * SM_STAGE;
#pragma unroll
        for (int j = 0; j < 4; j++) cp16(dA[j] + so, gA[j] + off);
#pragma unroll
        for (int j = 0; j < 4; j++) cp16(dB[j] + so, gB[j] + off);
        CP_COMMIT();
    }

    for (int it = 0; it < NITER; ++it) {
        if (it + STAGES - 1 < NITER)
            asm volatile("cp.async.wait_group %0;" :: "n"(STAGES - 2) : "memory");
        else
            asm volatile("cp.async.wait_group 0;" ::: "memory");
        __syncthreads();

        // Issue next stage (buffer was consumed 2 iterations ago; the
        // __syncthreads above orders the overwrite after everyone's compute).
        const int nxt = it + STAGES - 1;
        if (nxt < NITER) {
            const int off = nxt * 128;
            const uint32_t so = (nxt % STAGES) * SM_STAGE;
#pragma unroll
            for (int j = 0; j < 4; j++) cp16(dA[j] + so, gA[j] + off);
#pragma unroll
            for (int j = 0; j < 4; j++) cp16(dB[j] + so, gB[j] + off);
            CP_COMMIT();
        }

        const uint32_t st = sb + (it % STAGES) * SM_STAGE;
#pragma unroll
        for (int kk = 0; kk < 4; kk++) {
            uint32_t a[4][4], b[4][2];
#pragma unroll
            for (int i = 0; i < 4; i++)
                LDSM4(a[i][0], a[i][1], a[i][2], a[i][3],
                      st + ((aRaw + i * 2048 + kk * 32) ^ aX));
#pragma unroll
            for (int jj = 0; jj < 2; jj++) {
                uint32_t r0, r1, r2, r3;
                LDSM4(r0, r1, r2, r3,
                      st + 16384u + ((bRaw + jj * 2048 + kk * 32) ^ bX));
                b[2 * jj][0] = r0; b[2 * jj][1] = r1;
                b[2 * jj + 1][0] = r2; b[2 * jj + 1][1] = r3;
            }
#pragma unroll
            for (int i = 0; i < 4; i++)
#pragma unroll
                for (int j = 0; j < 4; j++)
                    MMA_TF32(acc[i][j], a[i], b[j]);
        }
    }

    // Epilogue: c0=(r, 2c), c1=(r, 2c+1), c2=(r+8, 2c), c3=(r+8, 2c+1)
    const int rr = lane >> 2;
    const int cc = (lane & 3) * 2;
#pragma unroll
    for (int i = 0; i < 4; i++) {
        const int m1 = wm + 16 * i + rr;
        const int m2 = m1 + 8;
        const int t1 = s_tok[m1], t2 = s_tok[m2];
        const float w1 = s_w[m1], w2 = s_w[m2];
        float* o1 = out + (size_t)(t1 < 0 ? 0 : t1) * HDIM + n0;
        float* o2 = out + (size_t)(t2 < 0 ? 0 : t2) * HDIM + n0;
#pragma unroll
        for (int j = 0; j < 4; j++) {
            const int n = wn + 8 * j + cc;
            if (t1 >= 0) {
                atomicAdd(o1 + n,     w1 * (acc[i][j][0] + s_be[n]));
                atomicAdd(o1 + n + 1, w1 * (acc[i][j][1] + s_be[n + 1]));
            }
            if (t2 >= 0) {
                atomicAdd(o2 + n,     w2 * (acc[i][j][2] + s_be[n]));
                atomicAdd(o2 + n + 1, w2 * (acc[i][j][3] + s_be[n + 1]));
            }
        }
    }
}

// ---------------------------------------------------------------------------
// Launch
// ---------------------------------------------------------------------------
extern "C" void kernel_launch(void* const* d_in, const int* in_sizes, int n_in,
                              void* d_out, int out_size) {
    const float* x  = (const float*)d_in[0];   // [N, D]
    const float* Wg = (const float*)d_in[1];   // [D, E]
    const float* bg = (const float*)d_in[2];   // [E]
    const float* We = (const float*)d_in[3];   // [E, D, H]
    const float* be = (const float*)d_in[4];   // [E, H]
    float* out = (float*)d_out;                // [N, H]
    (void)in_sizes; (void)n_in;

    cudaFuncSetAttribute(k_moe_gemm,
                         cudaFuncAttributeMaxDynamicSharedMemorySize, SMEM_BYTES);

    // 0) reset counters + zero output
    k_zero_cnt<<<1, 32>>>();
    int n4 = out_size / 4;
    k_zero_out<<<(n4 + 255) / 256, 256>>>((float4*)out, n4);

    // R) round x to tf32
    {
        int xn4 = NTOK * DDIM / 4;
        k_round_x<<<(xn4 + 255) / 256, 256>>>((const float4*)x, xn4);
    }

    // T) transpose + round expert weights
    {
        dim3 g(DDIM / 32, HDIM / 32, NEXP);
        dim3 b(32, 8);
        k_transpose<<<g, b>>>(We);
    }

    // 1) gating
    k_gate<<<NTOK / 8, 256>>>(x, Wg, bg);

    // 2) grouped expert GEMM (mma.sync tf32)
    {
        dim3 grid(HDIM / BN, NTOK / BM, NEXP);
        k_moe_gemm<<<grid, 256, SMEM_BYTES>>>(be, out);
    }
}

// round 5
// speedup vs baseline: 9.2923x; 1.6755x over previous
#include <cuda_runtime.h>
#include <cuda_fp16.h>
#include <math.h>
#include <stdint.h>

// MoELayer_47193100648722: N=8192 tokens, D=2048, H=2048, E=8, top-2, fp32.
#define NTOK 8192
#define DDIM 2048
#define HDIM 2048
#define NEXP 8

#define BM 128
#define BN 128
#define BK 64          // halves per k-iter => 128B rows
#define STAGES 3
#define NITER (DDIM / BK)   // 32

// ---------------------------------------------------------------------------
// Device scratch (no cudaMalloc allowed)
// ---------------------------------------------------------------------------
__device__ int    g_cnt[NEXP];
__device__ int    g_tok[NEXP * NTOK];        // packed: token*2 + slot
__device__ float  g_wt [NEXP * NTOK];
__device__ __half g_We_h[(size_t)NEXP * DDIM * HDIM]; // [e][h][d], fp16
__device__ __half g_x_h [(size_t)NTOK * DDIM];        // x, fp16
__device__ float  g_part[2ull * NTOK * HDIM];         // per-slot partials

// ---------------------------------------------------------------------------
// Helpers (base sm_103-safe)
// ---------------------------------------------------------------------------
__device__ __forceinline__ uint32_t smem_u32(const void* p) {
    return (uint32_t)__cvta_generic_to_shared(p);
}
__device__ __forceinline__ void cp16(uint32_t dst, const void* src) {
    asm volatile("cp.async.cg.shared.global [%0], [%1], 16;" :: "r"(dst), "l"(src));
}
#define CP_COMMIT() asm volatile("cp.async.commit_group;" ::: "memory")
#define SWZ(o) ((o) ^ (((o) >> 3) & 0x70))

#define LDSM4(R0, R1, R2, R3, addr)                                          \
    asm volatile("ldmatrix.sync.aligned.m8n8.x4.shared.b16 {%0,%1,%2,%3}, [%4];" \
                 : "=r"(R0), "=r"(R1), "=r"(R2), "=r"(R3) : "r"(addr))

#define MMA_F16(d, a, b)                                                     \
    asm volatile("mma.sync.aligned.m16n8k16.row.col.f32.f16.f16.f32 "        \
                 "{%0,%1,%2,%3}, {%4,%5,%6,%7}, {%8,%9}, {%0,%1,%2,%3};"     \
                 : "+f"((d)[0]), "+f"((d)[1]), "+f"((d)[2]), "+f"((d)[3])    \
                 : "r"((a)[0]), "r"((a)[1]), "r"((a)[2]), "r"((a)[3]),       \
                   "r"((b)[0]), "r"((b)[1]))

// ---------------------------------------------------------------------------
// Kernel 0: zero counters
// ---------------------------------------------------------------------------
__global__ void k_zero_cnt() {
    if (threadIdx.x < NEXP) g_cnt[threadIdx.x] = 0;
}

// ---------------------------------------------------------------------------
// Kernel R: convert x -> fp16 (8 floats -> 8 halves per thread)
// ---------------------------------------------------------------------------
__global__ void k_cvt_x(const float4* __restrict__ x, int n8) {
    int i = blockIdx.x * blockDim.x + threadIdx.x;
    if (i < n8) {
        float4 v0 = x[2 * i], v1 = x[2 * i + 1];
        __half2 h[4];
        h[0] = __floats2half2_rn(v0.x, v0.y);
        h[1] = __floats2half2_rn(v0.z, v0.w);
        h[2] = __floats2half2_rn(v1.x, v1.y);
        h[3] = __floats2half2_rn(v1.z, v1.w);
        ((uint4*)g_x_h)[i] = *(uint4*)h;
    }
}

// ---------------------------------------------------------------------------
// Kernel T: transpose We[e][d][h] -> g_We_h[e][h][d] (fp16), half2 stores.
// grid (D/64, H/32, E), block (32, 8)
// ---------------------------------------------------------------------------
__global__ void k_transpose(const float* __restrict__ We) {
    __shared__ float tile[64][33];
    int e = blockIdx.z;
    int d0 = blockIdx.x * 64, h0 = blockIdx.y * 32;
    const float* src = We + (size_t)e * DDIM * HDIM;
    __half* dst = g_We_h + (size_t)e * HDIM * DDIM;
    int tx = threadIdx.x, ty = threadIdx.y;
#pragma unroll
    for (int j = 0; j < 8; j++)
        tile[ty + j * 8][tx] = src[(size_t)(d0 + ty + j * 8) * HDIM + h0 + tx];
    __syncthreads();
#pragma unroll
    for (int j = 0; j < 4; j++) {
        int hl = ty + j * 8;
        __half2 v = __floats2half2_rn(tile[2 * tx][hl], tile[2 * tx + 1][hl]);
        *(__half2*)(dst + (size_t)(h0 + hl) * DDIM + d0 + 2 * tx) = v;
    }
}

// ---------------------------------------------------------------------------
// Kernel 1: gating (one warp per token) — softmax, top-2, per-expert lists.
// Entry packs slot: token*2 + 0 for its first expert, +1 for its second.
// ---------------------------------------------------------------------------
__global__ void k_gate(const float* __restrict__ x,
                       const float* __restrict__ Wg,
                       const float* __restrict__ bg) {
    int gwarp = (blockIdx.x * blockDim.x + threadIdx.x) >> 5;
    int lane  = threadIdx.x & 31;
    if (gwarp >= NTOK) return;

    const float* xr = x + (size_t)gwarp * DDIM;
    float acc[NEXP];
#pragma unroll
    for (int e = 0; e < NEXP; e++) acc[e] = 0.f;

    for (int d = lane; d < DDIM; d += 32) {
        float xv = xr[d];
        const float4* wr = (const float4*)(Wg + (size_t)d * NEXP);
        float4 w0 = wr[0];
        float4 w1 = wr[1];
        acc[0] += xv * w0.x;  acc[1] += xv * w0.y;
        acc[2] += xv * w0.z;  acc[3] += xv * w0.w;
        acc[4] += xv * w1.x;  acc[5] += xv * w1.y;
        acc[6] += xv * w1.z;  acc[7] += xv * w1.w;
    }
#pragma unroll
    for (int e = 0; e < NEXP; e++) {
#pragma unroll
        for (int o = 16; o > 0; o >>= 1)
            acc[e] += __shfl_xor_sync(0xFFFFFFFFu, acc[e], o);
    }
    if (lane == 0) {
#pragma unroll
        for (int e = 0; e < NEXP; e++) acc[e] += bg[e];
        float m1 = acc[0]; int i1 = 0;
#pragma unroll
        for (int e = 1; e < NEXP; e++)
            if (acc[e] > m1) { m1 = acc[e]; i1 = e; }
        float m2 = -INFINITY; int i2 = 0;
#pragma unroll
        for (int e = 0; e < NEXP; e++) {
            if (e == i1) continue;
            if (acc[e] > m2) { m2 = acc[e]; i2 = e; }
        }
        float s = 0.f;
#pragma unroll
        for (int e = 0; e < NEXP; e++) s += __expf(acc[e] - m1);
        float inv = 1.f / s;
        float w1v = inv;
        float w2v = __expf(m2 - m1) * inv;

        int p1 = atomicAdd(&g_cnt[i1], 1);
        g_tok[i1 * NTOK + p1] = gwarp * 2;       // slot 0
        g_wt [i1 * NTOK + p1] = w1v;
        int p2 = atomicAdd(&g_cnt[i2], 1);
        g_tok[i2 * NTOK + p2] = gwarp * 2 + 1;   // slot 1
        g_wt [i2 * NTOK + p2] = w2v;
    }
}

// ---------------------------------------------------------------------------
// Kernel 2: grouped expert GEMM — mma.sync fp16 (m16n8k16), 3-stage cp.async.
//   C[128 tok x 128 h] per CTA. 8 warps in 2(m) x 4(n), each 64x32.
//   Epilogue: plain v2 stores into per-slot partial buffers (no atomics).
// SMEM: 3 stages x (A 16KB + B 16KB) = 96KB, then s_tok/s_w/s_be.
// ---------------------------------------------------------------------------
#define SM_STAGE 32768
#define SM_TOK   (STAGES * SM_STAGE)          // 98304
#define SM_W     (SM_TOK + 512)
#define SM_BE    (SM_W + 512)
#define SMEM_BYTES (SM_BE + 512)

__global__ void __launch_bounds__(256, 2)
k_moe_gemm(const float* __restrict__ be) {
    extern __shared__ char dsm[];
    const int e   = blockIdx.z;
    const int cnt = g_cnt[e];
    const int m0  = blockIdx.y * BM;
    if (m0 >= cnt) return;
    const int n0  = blockIdx.x * BN;
    const int tid = threadIdx.x;
    const uint32_t sb = smem_u32(dsm);

    int*   s_tok = (int*)(dsm + SM_TOK);
    float* s_w   = (float*)(dsm + SM_W);
    float* s_be  = (float*)(dsm + SM_BE);

    if (tid < BM) {
        int r = m0 + tid;
        int t; float w;
        if (r < cnt) { t = g_tok[e * NTOK + r]; w = g_wt[e * NTOK + r]; }
        else         { t = -1; w = 0.f; }
        s_tok[tid] = t; s_w[tid] = w;
        s_be[tid]  = be[e * HDIM + n0 + tid];
    }
    __syncthreads();

    // Per-thread cp.async sources + swizzled dsts. 128B rows (BK=64 halves).
    const char* gA[4]; const char* gB[4];
    uint32_t dA[4], dB[4];
    {
        const int c8 = (tid & 7) * 16;
#pragma unroll
        for (int j = 0; j < 4; j++) {
            int row = (tid + j * 256) >> 3;   // 0..127
            int pk = s_tok[row];
            int t = (pk < 0) ? 0 : (pk >> 1); // padded rows: garbage, masked later
            gA[j] = (const char*)(g_x_h + (size_t)t * DDIM) + c8;
            dA[j] = sb + SWZ(row * 128 + c8);
            gB[j] = (const char*)(g_We_h + ((size_t)e * HDIM + n0 + row) * DDIM) + c8;
            dB[j] = sb + 16384 + SWZ(row * 128 + c8);
        }
    }

    // ldmatrix raw offsets + constant per-thread swizzle XOR (invariant under
    // +i*2048 and +kk*32: row%8 and the xor-source bits don't change).
    const int lane = tid & 31, warp = tid >> 5;
    const int wm = (warp & 1) * 64, wn = (warp >> 1) * 32;
    const int lr = lane & 7, q = lane >> 3;
    const uint32_t aRaw = (uint32_t)(wm + lr + 8 * (q & 1)) * 128 + 16 * (q >> 1);
    const uint32_t aX   = (aRaw >> 3) & 0x70;
    const uint32_t bRaw = (uint32_t)(wn + lr + 8 * (q >> 1)) * 128 + 16 * (q & 1);
    const uint32_t bX   = (bRaw >> 3) & 0x70;

    float acc[4][4][4];
#pragma unroll
    for (int i = 0; i < 4; i++)
#pragma unroll
        for (int j = 0; j < 4; j++)
#pragma unroll
            for (int c = 0; c < 4; c++) acc[i][j][c] = 0.f;

#pragma unroll
    for (int s = 0; s < STAGES - 1; s++) {
        const int off = s * 128;                 // BK*2 bytes per k-iter
        const uint32_t so = s * SM_STAGE;
#pragma unroll
        for (int j = 0; j < 4; j++) cp16(dA[j] + so, gA[j] + off);
#pragma unroll
        for (int j = 0; j < 4; j++) cp16(dB[j] + so, gB[j] + off);
        CP_COMMIT();
    }

    for (int it = 0; it < NITER; ++it) {
        if (it + STAGES - 1 < NITER)
            asm volatile("cp.async.wait_group %0;" :: "n"(STAGES - 2) : "memory");
        else
            asm volatile("cp.async.wait_group 0;" ::: "memory");
        __syncthreads();

        const int nxt = it + STAGES - 1;
        if (nxt < NITER) {
            const int off = nxt * 128;
            const uint32_t so = (nxt % STAGES) * SM_STAGE;
#pragma unroll
            for (int j = 0; j < 4; j++) cp16(dA[j] + so, gA[j] + off);
#pragma unroll
            for (int j = 0; j < 4; j++) cp16(dB[j] + so, gB[j] + off);
            CP_COMMIT();
        }

        const uint32_t st = sb + (it % STAGES) * SM_STAGE;
#pragma unroll
        for (int kk = 0; kk < 4; kk++) {      // 4 x k16 per BK=64
            uint32_t a[4][4], b[4][2];
#pragma unroll
            for (int i = 0; i < 4; i++)
                LDSM4(a[i][0], a[i][1], a[i][2], a[i][3],
                      st + ((aRaw + i * 2048 + kk * 32) ^ aX));
#pragma unroll
            for (int jj = 0; jj < 2; jj++) {
                uint32_t r0, r1, r2, r3;
                LDSM4(r0, r1, r2, r3,
                      st + 16384u + ((bRaw + jj * 2048 + kk * 32) ^ bX));
                b[2 * jj][0] = r0; b[2 * jj][1] = r1;
                b[2 * jj + 1][0] = r2; b[2 * jj + 1][1] = r3;
            }
#pragma unroll
            for (int i = 0; i < 4; i++)
#pragma unroll
                for (int j = 0; j < 4; j++)
                    MMA_F16(acc[i][j], a[i], b[j]);
        }
    }

    // Epilogue: plain float2 stores into per-slot partial buffer.
    const int rr = lane >> 2;
    const int cc = (lane & 3) * 2;
#pragma unroll
    for (int i = 0; i < 4; i++) {
        const int m1 = wm + 16 * i + rr;
        const int m2 = m1 + 8;
        const int pk1 = s_tok[m1], pk2 = s_tok[m2];
        const float w1 = s_w[m1], w2 = s_w[m2];
        float* o1 = g_part + ((size_t)(pk1 & 1) * NTOK + (pk1 >> 1)) * HDIM + n0;
        float* o2 = g_part + ((size_t)(pk2 & 1) * NTOK + (pk2 >> 1)) * HDIM + n0;
#pragma unroll
        for (int j = 0; j < 4; j++) {
            const int n = wn + 8 * j + cc;
            if (pk1 >= 0) {
                float2 v = make_float2(w1 * (acc[i][j][0] + s_be[n]),
                                       w1 * (acc[i][j][1] + s_be[n + 1]));
                *(float2*)(o1 + n) = v;
            }
            if (pk2 >= 0) {
                float2 v = make_float2(w2 * (acc[i][j][2] + s_be[n]),
                                       w2 * (acc[i][j][3] + s_be[n + 1]));
                *(float2*)(o2 + n) = v;
            }
        }
    }
}

// ---------------------------------------------------------------------------
// Kernel 3: combine — out = part[slot0] + part[slot1]
// ---------------------------------------------------------------------------
__global__ void k_combine(float4* __restrict__ out, int n4) {
    int i = blockIdx.x * blockDim.x + threadIdx.x;
    if (i < n4) {
        float4 a = ((const float4*)g_part)[i];
        float4 b = ((const float4*)g_part)[(size_t)NTOK * HDIM / 4 + i];
        out[i] = make_float4(a.x + b.x, a.y + b.y, a.z + b.z, a.w + b.w);
    }
}

// ---------------------------------------------------------------------------
// Launch
// ---------------------------------------------------------------------------
extern "C" void kernel_launch(void* const* d_in, const int* in_sizes, int n_in,
                              void* d_out, int out_size) {
    const float* x  = (const float*)d_in[0];   // [N, D]
    const float* Wg = (const float*)d_in[1];   // [D, E]
    const float* bg = (const float*)d_in[2];   // [E]
    const float* We = (const float*)d_in[3];   // [E, D, H]
    const float* be = (const float*)d_in[4];   // [E, H]
    float* out = (float*)d_out;                // [N, H]
    (void)in_sizes; (void)n_in;

    cudaFuncSetAttribute(k_moe_gemm,
                         cudaFuncAttributeMaxDynamicSharedMemorySize, SMEM_BYTES);

    // 0) reset counters
    k_zero_cnt<<<1, 32>>>();

    // R) x -> fp16
    {
        int n8 = NTOK * DDIM / 8;
        k_cvt_x<<<(n8 + 255) / 256, 256>>>((const float4*)x, n8);
    }

    // T) transpose + convert expert weights -> fp16 [e][h][d]
    {
        dim3 g(DDIM / 64, HDIM / 32, NEXP);
        dim3 b(32, 8);
        k_transpose<<<g, b>>>(We);
    }

    // 1) gating
    k_gate<<<NTOK / 8, 256>>>(x, Wg, bg);

    // 2) grouped expert GEMM (mma.sync fp16)
    {
        dim3 grid(HDIM / BN, NTOK / BM, NEXP);
        k_moe_gemm<<<grid, 256, SMEM_BYTES>>>(be);
    }

    // 3) combine slots
    {
        int n4 = NTOK * HDIM / 4;
        k_combine<<<(n4 + 255) / 256, 256>>>((float4*)out, n4);
    }
}